// round 1
// baseline (speedup 1.0000x reference)
#include <cuda_runtime.h>
#include <cuda_bf16.h>
#include <stdint.h>

// ---------------- configuration ----------------
#define THREADS        256
#define ITERS          16
#define ROWS_PER_BLOCK (THREADS * ITERS)   // 4096
#define MAXB           8192                 // supports R up to 32M
#define SCAN_T         1024

#define SCORE_THRESHOLD 0.35f

// ---------------- device scratch (no allocs allowed) ----------------
__device__ int g_cnt [MAXB];
__device__ int g_cntF[MAXB];
__device__ int g_off [MAXB];
__device__ int g_offF[MAXB];
__device__ int g_total[2];

// ---------------- K1: per-block counts ----------------
__global__ void count_kernel(const float* __restrict__ det, int R) {
    int b = blockIdx.x, t = threadIdx.x;
    int base = b * ROWS_PER_BLOCK;
    int c = 0, cF = 0;
#pragma unroll
    for (int k = 0; k < ITERS; k++) {
        int idx = base + k * THREADS + t;
        if (idx < R) {
            float cls = det[(size_t)idx * 6 + 0];
            float sc  = det[(size_t)idx * 6 + 5];
            bool pF = (sc >= SCORE_THRESHOLD);
            cF += pF ? 1 : 0;
            c  += (pF && cls == 0.0f) ? 1 : 0;
        }
    }
    // warp reduce
#pragma unroll
    for (int o = 16; o > 0; o >>= 1) {
        c  += __shfl_down_sync(0xffffffffu, c,  o);
        cF += __shfl_down_sync(0xffffffffu, cF, o);
    }
    __shared__ int sw[8], swF[8];
    int lane = t & 31, warp = t >> 5;
    if (lane == 0) { sw[warp] = c; swF[warp] = cF; }
    __syncthreads();
    if (t == 0) {
        int s = 0, sF = 0;
#pragma unroll
        for (int w = 0; w < 8; w++) { s += sw[w]; sF += swF[w]; }
        g_cnt[b] = s; g_cntF[b] = sF;
    }
}

// ---------------- K2: single-block exclusive scan over block counts ----------------
__global__ void scan_kernel(int B, float* __restrict__ out, size_t R) {
    __shared__ int ts[SCAN_T], tsF[SCAN_T];
    int t = threadIdx.x;
    int v[8], vF[8];
    int s = 0, sF = 0;
    const int PER = MAXB / SCAN_T; // 8
#pragma unroll
    for (int k = 0; k < PER; k++) {
        int i = t * PER + k;
        v[k]  = (i < B) ? g_cnt[i]  : 0;
        vF[k] = (i < B) ? g_cntF[i] : 0;
        s += v[k]; sF += vF[k];
    }
    ts[t] = s; tsF[t] = sF;
    __syncthreads();
    // Hillis-Steele inclusive scan
    for (int off = 1; off < SCAN_T; off <<= 1) {
        int a  = (t >= off) ? ts[t - off]  : 0;
        int aF = (t >= off) ? tsF[t - off] : 0;
        __syncthreads();
        ts[t] += a; tsF[t] += aF;
        __syncthreads();
    }
    int run  = ts[t]  - s;
    int runF = tsF[t] - sF;
#pragma unroll
    for (int k = 0; k < PER; k++) {
        int i = t * PER + k;
        if (i < B) {
            g_off[i]  = run;  run  += v[k];
            g_offF[i] = runF; runF += vF[k];
        }
    }
    if (t == SCAN_T - 1) {
        int n  = ts[t];
        int nF = tsF[t];
        g_total[0] = n;
        g_total[1] = nF;
        out[11 * R + 0] = (float)n;
        out[11 * R + 1] = (float)nF;
    }
}

// ---------------- K3: stable scatter ----------------
__global__ void scatter_kernel(const float2* __restrict__ det2,
                               float* __restrict__ out, int R, size_t roisN) {
    int b = blockIdx.x, t = threadIdx.x;
    int lane = t & 31, warp = t >> 5;       // 8 warps
    unsigned ltmask = (1u << lane) - 1u;

    __shared__ int wo[8], woF[8];

    int run = 0, runF = 0;                  // only thread 0 uses these
    if (t == 0) { run = g_off[b]; runF = g_offF[b]; }

    int base = b * ROWS_PER_BLOCK;
    float* __restrict__ outFull = out + roisN;

#pragma unroll 1
    for (int k = 0; k < ITERS; k++) {
        int idx = base + k * THREADS + t;
        bool inb = (idx < R);
        float2 p0 = make_float2(0.f, 0.f), p1 = p0, p2 = make_float2(0.f, -1.f);
        if (inb) {
            const float2* r = det2 + (size_t)idx * 3;
            p0 = r[0]; p1 = r[1]; p2 = r[2];
        }
        // row = [cls, b0, b1, b2, b3, score]; p0=(cls,b0) p1=(b1,b2) p2=(b3,score)
        bool predF = inb && (p2.y >= SCORE_THRESHOLD);
        bool pred  = predF && (p0.x == 0.0f);

        unsigned m  = __ballot_sync(0xffffffffu, pred);
        unsigned mF = __ballot_sync(0xffffffffu, predF);

        __shared__ int wc[8], wcF[8];
        if (lane == 0) { wc[warp] = __popc(m); wcF[warp] = __popc(mF); }
        __syncthreads();
        if (t == 0) {
            int s = run, sF = runF;
#pragma unroll
            for (int w = 0; w < 8; w++) {
                wo[w] = s;   s  += wc[w];
                woF[w] = sF; sF += wcF[w];
            }
            run = s; runF = sF;
        }
        __syncthreads();

        if (pred) {
            size_t pos = (size_t)(wo[warp] + __popc(m & ltmask));
            float* o = out + pos * 5;
            o[0] = 0.0f;
            o[1] = p0.y; o[2] = p1.x; o[3] = p1.y; o[4] = p2.x;
        }
        if (predF) {
            size_t posF = (size_t)(woF[warp] + __popc(mF & ltmask));
            float2* oF = reinterpret_cast<float2*>(outFull) + posF * 3;
            oF[0] = p0; oF[1] = p1; oF[2] = p2;
        }
        __syncthreads();  // protect wo/wc reuse next iteration
    }
}

// ---------------- K4: zero the dynamic tails (float4 where possible) ----------------
__global__ void zero_tail_kernel(float* __restrict__ out, size_t R) {
    size_t i = (size_t)blockIdx.x * blockDim.x + threadIdx.x;
    size_t f = i * 4;
    size_t roisN = 5 * R;
    size_t fullN = 6 * R;

    if (f < roisN) {
        size_t zs = (size_t)g_total[0] * 5;
        size_t lo = f > zs ? f : zs;
        size_t hi = (f + 4 < roisN) ? f + 4 : roisN;
        if (lo >= hi) return;
        if (lo == f && hi == f + 4) {
            *reinterpret_cast<float4*>(out + f) = make_float4(0.f, 0.f, 0.f, 0.f);
        } else {
            for (size_t j = lo; j < hi; j++) out[j] = 0.0f;
        }
    } else {
        size_t g = f - roisN;
        if (g >= fullN) return;
        size_t zs = (size_t)g_total[1] * 6;
        size_t lo = g > zs ? g : zs;
        size_t hi = (g + 4 < fullN) ? g + 4 : fullN;
        if (lo >= hi) return;
        if (lo == g && hi == g + 4) {
            *reinterpret_cast<float4*>(out + roisN + g) = make_float4(0.f, 0.f, 0.f, 0.f);
        } else {
            for (size_t j = lo; j < hi; j++) out[roisN + j] = 0.0f;
        }
    }
}

// ---------------- launch ----------------
extern "C" void kernel_launch(void* const* d_in, const int* in_sizes, int n_in,
                              void* d_out, int out_size) {
    const float* det = (const float*)d_in[0];
    float* out = (float*)d_out;

    int R = in_sizes[0] / 6;                 // detections: (1, R, 6)
    int B = (R + ROWS_PER_BLOCK - 1) / ROWS_PER_BLOCK;
    size_t Rs = (size_t)R;
    size_t roisN = 5 * Rs;

    count_kernel<<<B, THREADS>>>(det, R);
    scan_kernel<<<1, SCAN_T>>>(B, out, Rs);
    scatter_kernel<<<B, THREADS>>>((const float2*)det, out, R, roisN);

    size_t totalFloats = 11 * Rs;            // rois + rois_full regions
    size_t quads = (totalFloats + 3) / 4;
    int zblocks = (int)((quads + THREADS - 1) / THREADS);
    zero_tail_kernel<<<zblocks, THREADS>>>(out, Rs);
}